// round 2
// baseline (speedup 1.0000x reference)
#include <cuda_runtime.h>
#include <cuda_bf16.h>
#include <cstdint>

#define NTOK_MAX (8 * 4096)
#define IN_F 1024
#define CUT1 5000
#define CUT2 20000

__device__ int g_cnt[2];
__device__ int g_idx0[NTOK_MAX];
__device__ int g_idx1[NTOK_MAX];

// ---------------------------------------------------------------------------
__global__ void init_k() {
    g_cnt[0] = 0;
    g_cnt[1] = 0;
}

__global__ void classify_k(const int* __restrict__ tokens, int n) {
    int i = blockIdx.x * blockDim.x + threadIdx.x;
    int t = (i < n) ? tokens[i] : -1;
    int c = (t >= CUT2) ? 1 : ((t >= CUT1) ? 0 : -1);
    int lane = threadIdx.x & 31;
#pragma unroll
    for (int cc = 0; cc < 2; ++cc) {
        unsigned m = __ballot_sync(0xffffffffu, c == cc);
        if (c == cc) {
            int leader = __ffs(m) - 1;
            int base = 0;
            if (lane == leader) base = atomicAdd(&g_cnt[cc], __popc(m));
            base = __shfl_sync(m, base, leader);
            int off = base + __popc(m & ((1u << lane) - 1u));
            if (cc == 0) g_idx0[off] = i;
            else         g_idx1[off] = i;
        }
    }
}

__global__ void head_copy_k(const int* __restrict__ tokens,
                            const float* __restrict__ head_emb,
                            float* __restrict__ out) {
    int p = blockIdx.x;
    int t = __ldg(&tokens[p]);
    if (t >= CUT1) return;
    const float4* src = (const float4*)(head_emb + (size_t)t * IN_F);
    float4* dst = (float4*)(out + (size_t)p * IN_F);
    dst[threadIdx.x]       = src[threadIdx.x];
    dst[threadIdx.x + 128] = src[threadIdx.x + 128];
}

// ---------------------------------------------------------------------------
__device__ __forceinline__ void ldsm_x4(uint32_t& r0, uint32_t& r1,
                                        uint32_t& r2, uint32_t& r3,
                                        const void* smem_ptr) {
    uint32_t addr = (uint32_t)__cvta_generic_to_shared(smem_ptr);
    asm volatile("ldmatrix.sync.aligned.m8n8.x4.shared.b16 {%0,%1,%2,%3}, [%4];"
                 : "=r"(r0), "=r"(r1), "=r"(r2), "=r"(r3) : "r"(addr));
}

__device__ __forceinline__ void mma16816(float* c, const uint32_t* a,
                                         uint32_t b0, uint32_t b1) {
    asm volatile(
        "mma.sync.aligned.m16n8k16.row.col.f32.bf16.bf16.f32 "
        "{%0,%1,%2,%3}, {%4,%5,%6,%7}, {%8,%9}, {%0,%1,%2,%3};"
        : "+f"(c[0]), "+f"(c[1]), "+f"(c[2]), "+f"(c[3])
        : "r"(a[0]), "r"(a[1]), "r"(a[2]), "r"(a[3]), "r"(b0), "r"(b1));
}

// Convert 8 fp32 to 8 bf16 (hi or residual-lo) and pack into uint4.
__device__ __forceinline__ uint4 cvt_pack8(const float* v, bool lo) {
    __nv_bfloat16 h[8];
#pragma unroll
    for (int i = 0; i < 8; i++) {
        __nv_bfloat16 hi = __float2bfloat16(v[i]);
        h[i] = lo ? __float2bfloat16(v[i] - __bfloat162float(hi)) : hi;
    }
    uint4 u;
    u.x = *(const uint32_t*)&h[0];
    u.y = *(const uint32_t*)&h[2];
    u.z = *(const uint32_t*)&h[4];
    u.w = *(const uint32_t*)&h[6];
    return u;
}

// ---------------------------------------------------------------------------
// Split-bf16 tensor-core tail GEMM.
// out[pos, n] = sum_k emb[tok-LOW, k] * w[n, k], K' = 3K expansion:
//   region 0: Ah*Bh, region 1: Al*Bh, region 2: Ah*Bl.
template <int K, int LOW, int C>
__global__ void __launch_bounds__(256, 2)
tail_mma_k(const float* __restrict__ emb,
           const float* __restrict__ w,
           const int* __restrict__ tokens,
           float* __restrict__ out) {
    constexpr int TM = 128, TN = 64;
    constexpr int LDA = 24, LDB = 24;       // padded stride (halves): LDSM conflict-free
    constexpr int CPK = K / 16;             // source chunks per region
    constexpr int NC = 3 * CPK;             // total K' chunks

    __shared__ __align__(16) __nv_bfloat16 As[2][TM][LDA];
    __shared__ __align__(16) __nv_bfloat16 Bs[2][TN][LDB];
    __shared__ int sPos[TM];
    __shared__ int sOff[TM];

    const int count = g_cnt[C];
    const int rowBase = blockIdx.x * TM;
    if (rowBase >= count) return;
    const int rem = min(TM, count - rowBase);
    const int n0 = blockIdx.y * TN;
    const int tid = threadIdx.x;
    const int lane = tid & 31;
    const int wid = tid >> 5;
    const int* idxList = (C == 0) ? g_idx0 : g_idx1;

    if (tid < TM) {
        int mm = (tid < rem) ? tid : 0;     // duplicate row 0 for OOB (stores guarded)
        int p = idxList[rowBase + mm];
        sPos[tid] = p;
        sOff[tid] = (__ldg(&tokens[p]) - LOW) * K;
    }
    __syncthreads();

    // ---- loader setup: 2 threads per A row (8 floats each); B uses tid<128
    const int aRow = tid >> 1;
    const int half = tid & 1;
    const float* aPtr = emb + sOff[aRow] + half * 8;
    const float* bPtr = w + (size_t)(n0 + (tid >> 1)) * K + half * 8;

    float ra[8], rb[8];
#pragma unroll
    for (int i = 0; i < 8; i++) { ra[i] = 0.f; rb[i] = 0.f; }

    // prologue: load chunk 0 (region 0, src 0)
    {
        float4 v0 = *(const float4*)(aPtr);
        float4 v1 = *(const float4*)(aPtr + 4);
        ra[0]=v0.x; ra[1]=v0.y; ra[2]=v0.z; ra[3]=v0.w;
        ra[4]=v1.x; ra[5]=v1.y; ra[6]=v1.z; ra[7]=v1.w;
        if (tid < 128) {
            float4 w0 = *(const float4*)(bPtr);
            float4 w1 = *(const float4*)(bPtr + 4);
            rb[0]=w0.x; rb[1]=w0.y; rb[2]=w0.z; rb[3]=w0.w;
            rb[4]=w1.x; rb[5]=w1.y; rb[6]=w1.z; rb[7]=w1.w;
        }
    }

    // ---- MMA setup: 8 warps as 4(M) x 2(N); warp tile 32x32
    const int wm = (wid & 3) * 32;
    const int wn = (wid >> 2) * 32;
    float c[2][4][4];
#pragma unroll
    for (int i = 0; i < 2; i++)
#pragma unroll
        for (int j = 0; j < 4; j++)
#pragma unroll
            for (int q = 0; q < 4; q++) c[i][j][q] = 0.f;

    // ldmatrix lane->address components
    const int aLdRow = (lane & 15);
    const int aLdCol = (lane >> 4) * 8;
    const int bLdRow = ((lane >> 4) << 3) + (lane & 7);
    const int bLdCol = (lane & 8);

    int buf = 0;
    for (int kc = 0; kc < NC; kc++) {
        // region/flags for the chunk being STORED (kc)
        int src = kc, reg = 0;
        if (src >= CPK) { src -= CPK; reg = 1; }
        if (src >= CPK) { src -= CPK; reg = 2; }
        bool aLo = (reg == 1);
        bool bLo = (reg == 2);

        *(uint4*)&As[buf][aRow][half * 8] = cvt_pack8(ra, aLo);
        if (tid < 128)
            *(uint4*)&Bs[buf][tid >> 1][half * 8] = cvt_pack8(rb, bLo);
        __syncthreads();

        // prefetch next chunk
        if (kc + 1 < NC) {
            int s2 = kc + 1;
            if (s2 >= CPK) s2 -= CPK;
            if (s2 >= CPK) s2 -= CPK;
            const float* p = aPtr + s2 * 16;
            float4 v0 = *(const float4*)(p);
            float4 v1 = *(const float4*)(p + 4);
            ra[0]=v0.x; ra[1]=v0.y; ra[2]=v0.z; ra[3]=v0.w;
            ra[4]=v1.x; ra[5]=v1.y; ra[6]=v1.z; ra[7]=v1.w;
            if (tid < 128) {
                const float* q = bPtr + s2 * 16;
                float4 w0 = *(const float4*)(q);
                float4 w1 = *(const float4*)(q + 4);
                rb[0]=w0.x; rb[1]=w0.y; rb[2]=w0.z; rb[3]=w0.w;
                rb[4]=w1.x; rb[5]=w1.y; rb[6]=w1.z; rb[7]=w1.w;
            }
        }

        // MMA on buffer `buf`
        uint32_t aF[2][4], bF[2][4];
#pragma unroll
        for (int mf = 0; mf < 2; mf++)
            ldsm_x4(aF[mf][0], aF[mf][1], aF[mf][2], aF[mf][3],
                    &As[buf][wm + mf * 16 + aLdRow][aLdCol]);
#pragma unroll
        for (int g = 0; g < 2; g++)
            ldsm_x4(bF[g][0], bF[g][1], bF[g][2], bF[g][3],
                    &Bs[buf][wn + g * 16 + bLdRow][bLdCol]);
#pragma unroll
        for (int mf = 0; mf < 2; mf++)
#pragma unroll
            for (int nf = 0; nf < 4; nf++)
                mma16816(c[mf][nf], aF[mf],
                         bF[nf >> 1][(nf & 1) * 2], bF[nf >> 1][(nf & 1) * 2 + 1]);

        __syncthreads();
        buf ^= 1;
    }

    // ---- epilogue: scatter-store
#pragma unroll
    for (int mf = 0; mf < 2; mf++) {
#pragma unroll
        for (int nf = 0; nf < 4; nf++) {
            int r0 = wm + mf * 16 + (lane >> 2);
            int col = n0 + wn + nf * 8 + 2 * (lane & 3);
            if (r0 < rem) {
                float2 v = make_float2(c[mf][nf][0], c[mf][nf][1]);
                *(float2*)(out + (size_t)sPos[r0] * IN_F + col) = v;
            }
            int r1 = r0 + 8;
            if (r1 < rem) {
                float2 v = make_float2(c[mf][nf][2], c[mf][nf][3]);
                *(float2*)(out + (size_t)sPos[r1] * IN_F + col) = v;
            }
        }
    }
}

// ---------------------------------------------------------------------------
extern "C" void kernel_launch(void* const* d_in, const int* in_sizes, int n_in,
                              void* d_out, int out_size) {
    const int*   tokens   = (const int*)d_in[0];
    const float* head_emb = (const float*)d_in[1];
    const float* t0e      = (const float*)d_in[2];
    const float* t0w      = (const float*)d_in[3];
    const float* t1e      = (const float*)d_in[4];
    const float* t1w      = (const float*)d_in[5];
    float* out = (float*)d_out;
    int n = in_sizes[0];
    if (n > NTOK_MAX) n = NTOK_MAX;

    init_k<<<1, 1>>>();
    classify_k<<<(n + 255) / 256, 256>>>(tokens, n);
    head_copy_k<<<n, 128>>>(tokens, head_emb, out);

    dim3 grid((n + 127) / 128, IN_F / 64);
    tail_mma_k<512, CUT1, 0><<<grid, 256>>>(t0e, t0w, tokens, out);
    tail_mma_k<256, CUT2, 1><<<grid, 256>>>(t1e, t1w, tokens, out);
}